// round 4
// baseline (speedup 1.0000x reference)
#include <cuda_runtime.h>
#include <cuda_bf16.h>
#include <math.h>

// Problem constants (B=2, N=2048, H=64, EPS=0.01)
#define HN 64
#define EPS2f 0.0001f

// Table over d2 in [~9.92e-5, 4096], indexed by float bit pattern.
// BASE aligned to 1<<SHIFT; 2^(23-SHIFT) samples per binade.
#define TAB_SHIFT 12
#define TAB_BASE  0x38D00000        // 9.918e-5f  (< 1e-4 = 0x38D1B717)
#define TAB_TOP   0x45800000        // 4096.0f
#define TAB_ENTRIES ((TAB_TOP - TAB_BASE) >> TAB_SHIFT)   // 51968

__device__ float  g_vals[TAB_ENTRIES + 1];
__device__ float2 g_tab[TAB_ENTRIES];

// ---------------------------------------------------------------------------
// Kernel 1: evaluate the MLP m(d2) at every table grid point.
// ---------------------------------------------------------------------------
__global__ __launch_bounds__(128)
void build_table_kernel(const float* __restrict__ W1, const float* __restrict__ b1,
                        const float* __restrict__ W2, const float* __restrict__ b2,
                        const float* __restrict__ W3, const float* __restrict__ b3)
{
    __shared__ float sW2[HN * HN];
    __shared__ float sW1a[HN], sW1b[HN], sb1[HN], sW3[HN], sb2[HN];

    for (int t = threadIdx.x; t < HN * HN; t += blockDim.x) sW2[t] = W2[t];
    if (threadIdx.x < HN) {
        sW1a[threadIdx.x] = W1[threadIdx.x];        // W1[0][k]
        sW1b[threadIdx.x] = W1[HN + threadIdx.x];   // W1[1][k]
        sb1[threadIdx.x]  = b1[threadIdx.x];
        sW3[threadIdx.x]  = W3[threadIdx.x];
        sb2[threadIdx.x]  = b2[threadIdx.x];
    }
    __syncthreads();

    int k = blockIdx.x * blockDim.x + threadIdx.x;
    if (k > TAB_ENTRIES) return;

    float d2   = __int_as_float(TAB_BASE + (k << TAB_SHIFT));
    float dist = sqrtf(d2);
    float invc = 1.0f / (d2 * dist);

    float h1[HN];
#pragma unroll
    for (int a = 0; a < HN; a++) {
        float z = fmaf(dist, sW1a[a], fmaf(invc, sW1b[a], sb1[a]));
        h1[a] = fmaxf(z, 0.0f);
    }

    float m = b3[0];
    for (int c = 0; c < HN; c++) {
        float z = sb2[c];
#pragma unroll
        for (int a = 0; a < HN; a++)
            z = fmaf(h1[a], sW2[a * HN + c], z);
        m = fmaf(fmaxf(z, 0.0f), sW3[c], m);
    }
    g_vals[k] = m;
}

// ---------------------------------------------------------------------------
// Kernel 2: pack (value, slope) per interval for single-LDG.64 lerp.
// ---------------------------------------------------------------------------
__global__ __launch_bounds__(256)
void pack_table_kernel()
{
    int k = blockIdx.x * blockDim.x + threadIdx.x;
    if (k >= TAB_ENTRIES) return;
    float x0 = __int_as_float(TAB_BASE + (k << TAB_SHIFT));
    float x1 = __int_as_float(TAB_BASE + ((k + 1) << TAB_SHIFT));
    float v0 = g_vals[k];
    float v1 = g_vals[k + 1];
    g_tab[k] = make_float2(v0, (v1 - v0) / (x1 - x0));
}

// ---------------------------------------------------------------------------
// Kernel 3: zero the output (harness poisons it).
// ---------------------------------------------------------------------------
__global__ void zero_kernel(float* __restrict__ out, int n)
{
    int t = blockIdx.x * blockDim.x + threadIdx.x;
    if (t < n) out[t] = 0.0f;
}

// ---------------------------------------------------------------------------
// Kernel 4: tiled all-pairs force accumulation.
//   acc_i = sum_{j} m(d2_ij) * (pos_j - pos_i)        (j==i term is 0)
// Block: 128 threads, each owns one i; iterates a 128-wide j chunk from smem.
// ---------------------------------------------------------------------------
#define IT 128
#define JC 128

__global__ __launch_bounds__(IT)
void forces_kernel(const float* __restrict__ pos, float* __restrict__ out, int N)
{
    const int b  = blockIdx.z;
    const int i  = blockIdx.y * IT + threadIdx.x;
    const int j0 = blockIdx.x * JC;
    const float* p = pos + (size_t)b * N * 3;

    __shared__ float sx[JC], sy[JC], sz[JC];
    {
        int t = threadIdx.x;             // IT == JC: one element per thread
        int j = j0 + t;
        sx[t] = p[j * 3 + 0];
        sy[t] = p[j * 3 + 1];
        sz[t] = p[j * 3 + 2];
    }
    __syncthreads();

    const float xi = p[i * 3 + 0];
    const float yi = p[i * 3 + 1];
    const float zi = p[i * 3 + 2];

    float ax = 0.0f, ay = 0.0f, az = 0.0f;

#pragma unroll 16
    for (int t = 0; t < JC; t++) {
        float dx = sx[t] - xi;
        float dy = sy[t] - yi;
        float dz = sz[t] - zi;
        float d2 = fmaf(dx, dx, fmaf(dy, dy, fmaf(dz, dz, EPS2f)));

        int bits = __float_as_int(d2);
        bits = min(max(bits, (int)TAB_BASE), (int)TAB_TOP - 1);
        int kb = bits & ~((1 << TAB_SHIFT) - 1);
        float2 ts = g_tab[(kb - (int)TAB_BASE) >> TAB_SHIFT];
        float m = fmaf(d2 - __int_as_float(kb), ts.y, ts.x);

        ax = fmaf(m, dx, ax);
        ay = fmaf(m, dy, ay);
        az = fmaf(m, dz, az);
    }

    float* o = out + ((size_t)b * N + i) * 3;
    atomicAdd(o + 0, ax);
    atomicAdd(o + 1, ay);
    atomicAdd(o + 2, az);
}

// ---------------------------------------------------------------------------
// Launch
// ---------------------------------------------------------------------------
extern "C" void kernel_launch(void* const* d_in, const int* in_sizes, int n_in,
                              void* d_out, int out_size)
{
    const float* pos = (const float*)d_in[0];
    const float* W1  = (const float*)d_in[1];
    const float* b1  = (const float*)d_in[2];
    const float* W2  = (const float*)d_in[3];
    const float* b2  = (const float*)d_in[4];
    const float* W3  = (const float*)d_in[5];
    const float* b3  = (const float*)d_in[6];
    float* out = (float*)d_out;

    const int N = 2048;
    const int B = in_sizes[0] / (N * 3);   // = 2

    // 1) build m(d2) table from this launch's weights
    {
        int threads = 128;
        int blocks = (TAB_ENTRIES + 1 + threads - 1) / threads;
        build_table_kernel<<<blocks, threads>>>(W1, b1, W2, b2, W3, b3);
    }
    // 2) pack (value, slope)
    {
        int threads = 256;
        int blocks = (TAB_ENTRIES + threads - 1) / threads;
        pack_table_kernel<<<blocks, threads>>>();
    }
    // 3) zero output
    {
        int n = out_size;
        zero_kernel<<<(n + 255) / 256, 256>>>(out, n);
    }
    // 4) main all-pairs accumulation
    {
        dim3 grid(N / JC, N / IT, B);
        forces_kernel<<<grid, IT>>>(pos, out, N);
    }
}

// round 5
// speedup vs baseline: 1.0030x; 1.0030x over previous
#include <cuda_runtime.h>
#include <cuda_bf16.h>
#include <math.h>

// Problem constants (B=2, N=2048, H=64, EPS=0.01)
#define HN 64
#define EPS2f 0.0001f

// Table over d2 in [~9.92e-5, 4096], indexed by float bit pattern.
// BASE aligned to 1<<SHIFT; 2^(23-SHIFT) samples per binade.
#define TAB_SHIFT 12
#define TAB_BASE  0x38D00000        // 9.918e-5f  (< 1e-4 = 0x38D1B717)
#define TAB_TOP   0x45800000        // 4096.0f
#define TAB_ENTRIES ((TAB_TOP - TAB_BASE) >> TAB_SHIFT)   // 51968

__device__ float  g_vals[TAB_ENTRIES + 1];
__device__ float2 g_tab[TAB_ENTRIES];

// ---------------------------------------------------------------------------
// Kernel 1: evaluate the MLP m(d2) at every table grid point.
// ---------------------------------------------------------------------------
__global__ __launch_bounds__(128)
void build_table_kernel(const float* __restrict__ W1, const float* __restrict__ b1,
                        const float* __restrict__ W2, const float* __restrict__ b2,
                        const float* __restrict__ W3, const float* __restrict__ b3)
{
    __shared__ float sW2[HN * HN];
    __shared__ float sW1a[HN], sW1b[HN], sb1[HN], sW3[HN], sb2[HN];

    for (int t = threadIdx.x; t < HN * HN; t += blockDim.x) sW2[t] = W2[t];
    if (threadIdx.x < HN) {
        sW1a[threadIdx.x] = W1[threadIdx.x];        // W1[0][k]
        sW1b[threadIdx.x] = W1[HN + threadIdx.x];   // W1[1][k]
        sb1[threadIdx.x]  = b1[threadIdx.x];
        sW3[threadIdx.x]  = W3[threadIdx.x];
        sb2[threadIdx.x]  = b2[threadIdx.x];
    }
    __syncthreads();

    int k = blockIdx.x * blockDim.x + threadIdx.x;
    if (k > TAB_ENTRIES) return;

    float d2   = __int_as_float(TAB_BASE + (k << TAB_SHIFT));
    float dist = sqrtf(d2);
    float invc = 1.0f / (d2 * dist);

    float h1[HN];
#pragma unroll
    for (int a = 0; a < HN; a++) {
        float z = fmaf(dist, sW1a[a], fmaf(invc, sW1b[a], sb1[a]));
        h1[a] = fmaxf(z, 0.0f);
    }

    float m = b3[0];
    for (int c = 0; c < HN; c++) {
        float z = sb2[c];
#pragma unroll
        for (int a = 0; a < HN; a++)
            z = fmaf(h1[a], sW2[a * HN + c], z);
        m = fmaf(fmaxf(z, 0.0f), sW3[c], m);
    }
    g_vals[k] = m;
}

// ---------------------------------------------------------------------------
// Kernel 2: pack (value, slope) per interval for single-LDG.64 lerp.
// ---------------------------------------------------------------------------
__global__ __launch_bounds__(256)
void pack_table_kernel()
{
    int k = blockIdx.x * blockDim.x + threadIdx.x;
    if (k >= TAB_ENTRIES) return;
    float x0 = __int_as_float(TAB_BASE + (k << TAB_SHIFT));
    float x1 = __int_as_float(TAB_BASE + ((k + 1) << TAB_SHIFT));
    float v0 = g_vals[k];
    float v1 = g_vals[k + 1];
    g_tab[k] = make_float2(v0, (v1 - v0) / (x1 - x0));
}

// ---------------------------------------------------------------------------
// Kernel 3: zero the output (harness poisons it).
// ---------------------------------------------------------------------------
__global__ void zero_kernel(float* __restrict__ out, int n)
{
    int t = blockIdx.x * blockDim.x + threadIdx.x;
    if (t < n) out[t] = 0.0f;
}

// ---------------------------------------------------------------------------
// Kernel 4: tiled all-pairs force accumulation.
//   acc_i = sum_{j} m(d2_ij) * (pos_j - pos_i)        (j==i term is 0)
// Block: 128 threads, each owns one i; iterates a 128-wide j chunk from smem.
// ---------------------------------------------------------------------------
#define IT 128
#define JC 128

__global__ __launch_bounds__(IT)
void forces_kernel(const float* __restrict__ pos, float* __restrict__ out, int N)
{
    const int b  = blockIdx.z;
    const int i  = blockIdx.y * IT + threadIdx.x;
    const int j0 = blockIdx.x * JC;
    const float* p = pos + (size_t)b * N * 3;

    __shared__ float sx[JC], sy[JC], sz[JC];
    {
        int t = threadIdx.x;             // IT == JC: one element per thread
        int j = j0 + t;
        sx[t] = p[j * 3 + 0];
        sy[t] = p[j * 3 + 1];
        sz[t] = p[j * 3 + 2];
    }
    __syncthreads();

    const float xi = p[i * 3 + 0];
    const float yi = p[i * 3 + 1];
    const float zi = p[i * 3 + 2];

    float ax = 0.0f, ay = 0.0f, az = 0.0f;

#pragma unroll 16
    for (int t = 0; t < JC; t++) {
        float dx = sx[t] - xi;
        float dy = sy[t] - yi;
        float dz = sz[t] - zi;
        float d2 = fmaf(dx, dx, fmaf(dy, dy, fmaf(dz, dz, EPS2f)));

        int bits = __float_as_int(d2);
        bits = min(max(bits, (int)TAB_BASE), (int)TAB_TOP - 1);
        int kb = bits & ~((1 << TAB_SHIFT) - 1);
        float2 ts = g_tab[(kb - (int)TAB_BASE) >> TAB_SHIFT];
        float m = fmaf(d2 - __int_as_float(kb), ts.y, ts.x);

        ax = fmaf(m, dx, ax);
        ay = fmaf(m, dy, ay);
        az = fmaf(m, dz, az);
    }

    float* o = out + ((size_t)b * N + i) * 3;
    atomicAdd(o + 0, ax);
    atomicAdd(o + 1, ay);
    atomicAdd(o + 2, az);
}

// ---------------------------------------------------------------------------
// Launch
// ---------------------------------------------------------------------------
extern "C" void kernel_launch(void* const* d_in, const int* in_sizes, int n_in,
                              void* d_out, int out_size)
{
    const float* pos = (const float*)d_in[0];
    const float* W1  = (const float*)d_in[1];
    const float* b1  = (const float*)d_in[2];
    const float* W2  = (const float*)d_in[3];
    const float* b2  = (const float*)d_in[4];
    const float* W3  = (const float*)d_in[5];
    const float* b3  = (const float*)d_in[6];
    float* out = (float*)d_out;

    const int N = 2048;
    const int B = in_sizes[0] / (N * 3);   // = 2

    // 1) build m(d2) table from this launch's weights
    {
        int threads = 128;
        int blocks = (TAB_ENTRIES + 1 + threads - 1) / threads;
        build_table_kernel<<<blocks, threads>>>(W1, b1, W2, b2, W3, b3);
    }
    // 2) pack (value, slope)
    {
        int threads = 256;
        int blocks = (TAB_ENTRIES + threads - 1) / threads;
        pack_table_kernel<<<blocks, threads>>>();
    }
    // 3) zero output
    {
        int n = out_size;
        zero_kernel<<<(n + 255) / 256, 256>>>(out, n);
    }
    // 4) main all-pairs accumulation
    {
        dim3 grid(N / JC, N / IT, B);
        forces_kernel<<<grid, IT>>>(pos, out, N);
    }
}

// round 6
// speedup vs baseline: 1.7026x; 1.6976x over previous
#include <cuda_runtime.h>
#include <cuda_bf16.h>
#include <math.h>

// Problem constants (B=2, N=2048, H=64, EPS=0.01)
#define HN 64
#define EPS2f 0.0001f

// Table over d2 in [~9.92e-5, 4096], indexed by float bit pattern.
// BASE aligned to 1<<SHIFT; 2^(23-SHIFT)=512 samples per binade.
#define TAB_SHIFT 14
#define TAB_BASE  0x38D00000        // 9.918e-5f  (< 1e-4 = EPS^2)
#define TAB_TOP   0x45800000        // 4096.0f
#define TAB_ENTRIES ((TAB_TOP - TAB_BASE) >> TAB_SHIFT)   // 12992

__device__ float  g_vals[TAB_ENTRIES + 1];
__device__ float2 g_tab[TAB_ENTRIES];   // (intercept c0 = v0 - x0*s, slope s)

// ---------------------------------------------------------------------------
// Kernel 1: evaluate MLP m(d2) at every grid point.
// 4 threads per point; thread q owns output columns c = cc*4 + q (conflict-free
// LDS multicast: 4 consecutive addresses per instruction). 4-way ILP in the
// GEMV chain; shfl-reduce the 4 partials.
// ---------------------------------------------------------------------------
__global__ __launch_bounds__(128)
void build_table_kernel(const float* __restrict__ W1, const float* __restrict__ b1,
                        const float* __restrict__ W2, const float* __restrict__ b2,
                        const float* __restrict__ W3, const float* __restrict__ b3)
{
    __shared__ float sW2[HN * HN];
    __shared__ float sW1a[HN], sW1b[HN], sb1[HN], sW3[HN], sb2[HN];

    for (int t = threadIdx.x; t < HN * HN; t += blockDim.x) sW2[t] = W2[t];
    if (threadIdx.x < HN) {
        sW1a[threadIdx.x] = W1[threadIdx.x];        // W1[0][k]
        sW1b[threadIdx.x] = W1[HN + threadIdx.x];   // W1[1][k]
        sb1[threadIdx.x]  = b1[threadIdx.x];
        sW3[threadIdx.x]  = W3[threadIdx.x];
        sb2[threadIdx.x]  = b2[threadIdx.x];
    }
    __syncthreads();

    int g  = blockIdx.x * blockDim.x + threadIdx.x;
    int k0 = g >> 2;                 // grid point
    int q  = g & 3;                  // column-quarter
    int k  = min(k0, TAB_ENTRIES);   // clamp so every lane joins the shfl

    float d2   = __int_as_float(TAB_BASE + (k << TAB_SHIFT));
    float dist = sqrtf(d2);
    float invc = 1.0f / (d2 * dist);

    float h1[HN];
#pragma unroll
    for (int a = 0; a < HN; a++) {
        float z = fmaf(dist, sW1a[a], fmaf(invc, sW1b[a], sb1[a]));
        h1[a] = fmaxf(z, 0.0f);
    }

    float m = 0.0f;
#pragma unroll 4
    for (int cc = 0; cc < HN / 4; cc++) {
        int c = cc * 4 + q;
        float z0 = 0.f, z1 = 0.f, z2 = 0.f, z3 = 0.f;
#pragma unroll
        for (int a = 0; a < HN; a += 4) {
            z0 = fmaf(h1[a + 0], sW2[(a + 0) * HN + c], z0);
            z1 = fmaf(h1[a + 1], sW2[(a + 1) * HN + c], z1);
            z2 = fmaf(h1[a + 2], sW2[(a + 2) * HN + c], z2);
            z3 = fmaf(h1[a + 3], sW2[(a + 3) * HN + c], z3);
        }
        float z = ((z0 + z1) + (z2 + z3)) + sb2[c];
        m = fmaf(fmaxf(z, 0.0f), sW3[c], m);
    }

    // reduce the 4 column-quarter partials (groups of 4 lanes are aligned)
    m += __shfl_xor_sync(0xffffffffu, m, 1);
    m += __shfl_xor_sync(0xffffffffu, m, 2);

    if (q == 0 && k0 <= TAB_ENTRIES)
        g_vals[k0] = m + b3[0];
}

// ---------------------------------------------------------------------------
// Kernel 2 (fused): zero the output AND pack (intercept, slope) per interval.
// ---------------------------------------------------------------------------
__global__ __launch_bounds__(256)
void pack_zero_kernel(float* __restrict__ out, int out_n)
{
    int k = blockIdx.x * blockDim.x + threadIdx.x;
    if (k < out_n) out[k] = 0.0f;
    if (k < TAB_ENTRIES) {
        float x0 = __int_as_float(TAB_BASE + (k << TAB_SHIFT));
        float x1 = __int_as_float(TAB_BASE + ((k + 1) << TAB_SHIFT));
        float v0 = g_vals[k];
        float v1 = g_vals[k + 1];
        float s  = (v1 - v0) / (x1 - x0);
        g_tab[k] = make_float2(fmaf(-x0, s, v0), s);   // m(d2) = c0 + d2*s
    }
}

// ---------------------------------------------------------------------------
// Kernel 3: tiled all-pairs force accumulation.
//   acc_i = sum_j m(d2_ij) * (pos_j - pos_i)     (j==i term is exactly 0)
// IT=128 i's per block, JC=64 j's per block -> 1024 blocks (occ ~43%).
// ---------------------------------------------------------------------------
#define IT 128
#define JC 64

__global__ __launch_bounds__(IT)
void forces_kernel(const float* __restrict__ pos, float* __restrict__ out, int N)
{
    const int b  = blockIdx.z;
    const int i  = blockIdx.y * IT + threadIdx.x;
    const int j0 = blockIdx.x * JC;
    const float* p = pos + (size_t)b * N * 3;

    __shared__ float4 sj[JC];
    if (threadIdx.x < JC) {
        int j = j0 + threadIdx.x;
        sj[threadIdx.x] = make_float4(p[j * 3 + 0], p[j * 3 + 1], p[j * 3 + 2], 0.0f);
    }
    __syncthreads();

    const float xi = p[i * 3 + 0];
    const float yi = p[i * 3 + 1];
    const float zi = p[i * 3 + 2];

    float ax = 0.0f, ay = 0.0f, az = 0.0f;
    const float2* __restrict__ tab = g_tab;

#pragma unroll 16
    for (int t = 0; t < JC; t++) {
        float4 pj = sj[t];
        float dx = pj.x - xi;
        float dy = pj.y - yi;
        float dz = pj.z - zi;
        float d2 = fmaf(dx, dx, fmaf(dy, dy, fmaf(dz, dz, EPS2f)));

        int bits = __float_as_int(d2);
        bits = max(min(bits, (int)TAB_TOP - 1), (int)TAB_BASE);
        float2 ts = tab[(unsigned)(bits - (int)TAB_BASE) >> TAB_SHIFT];
        float m = fmaf(d2, ts.y, ts.x);

        ax = fmaf(m, dx, ax);
        ay = fmaf(m, dy, ay);
        az = fmaf(m, dz, az);
    }

    float* o = out + ((size_t)b * N + i) * 3;
    atomicAdd(o + 0, ax);
    atomicAdd(o + 1, ay);
    atomicAdd(o + 2, az);
}

// ---------------------------------------------------------------------------
// Launch
// ---------------------------------------------------------------------------
extern "C" void kernel_launch(void* const* d_in, const int* in_sizes, int n_in,
                              void* d_out, int out_size)
{
    const float* pos = (const float*)d_in[0];
    const float* W1  = (const float*)d_in[1];
    const float* b1  = (const float*)d_in[2];
    const float* W2  = (const float*)d_in[3];
    const float* b2  = (const float*)d_in[4];
    const float* W3  = (const float*)d_in[5];
    const float* b3  = (const float*)d_in[6];
    float* out = (float*)d_out;

    const int N = 2048;
    const int B = in_sizes[0] / (N * 3);   // = 2

    // 1) build m(d2) table: 4 threads per point
    {
        int threads = 128;
        int total = (TAB_ENTRIES + 1) * 4;
        int blocks = (total + threads - 1) / threads;
        build_table_kernel<<<blocks, threads>>>(W1, b1, W2, b2, W3, b3);
    }
    // 2) fused: zero output + pack (intercept, slope)
    {
        int threads = 256;
        int n = out_size > TAB_ENTRIES ? out_size : TAB_ENTRIES;
        pack_zero_kernel<<<(n + threads - 1) / threads, threads>>>(out, out_size);
    }
    // 3) main all-pairs accumulation
    {
        dim3 grid(N / JC, N / IT, B);
        forces_kernel<<<grid, IT>>>(pos, out, N);
    }
}

// round 7
// speedup vs baseline: 2.5219x; 1.4811x over previous
#include <cuda_runtime.h>
#include <cuda_bf16.h>
#include <math.h>

// Problem constants (B=2, N=2048, H=64, EPS=0.01)
#define HN 64
#define EPS2f 0.0001f

// Table over d2 in [~9.92e-5, 4096], indexed by float bit pattern.
// BASE aligned to 1<<SHIFT; 2^(23-SHIFT)=128 samples per binade.
#define TAB_SHIFT 16
#define TAB_BASE  0x38D00000        // 9.918e-5f  (< 1e-4 = EPS^2, so no lower clamp needed)
#define TAB_TOP   0x45800000        // 4096.0f
#define TAB_ENTRIES ((TAB_TOP - TAB_BASE) >> TAB_SHIFT)   // 3248

__device__ float  g_vals[TAB_ENTRIES + 1];
__device__ float2 g_tab[TAB_ENTRIES];   // (intercept c0 = v0 - x0*s, slope s)

// ---------------------------------------------------------------------------
// Kernel 1: evaluate MLP m(d2) at every grid point — cooperative version.
// 128 threads handle 8 points. Thread (p = tid>>4, q = tid&15):
//   phase 1: computes h1[p][q*4 .. q*4+4) into smem (padded stride 68)
//   phase 2: float4 GEMV slice over columns [q*4, q*4+4)
//   phase 3: relu + W3 dot, 16-lane shfl reduce, lane q==0 writes.
// ---------------------------------------------------------------------------
#define PPB 8
#define H1S 68   // padded h1 row stride (68*4B = 272B: 16B-aligned, bank-shifted)

__global__ __launch_bounds__(128)
void build_table_kernel(const float* __restrict__ W1, const float* __restrict__ b1,
                        const float* __restrict__ W2, const float* __restrict__ b2,
                        const float* __restrict__ W3, const float* __restrict__ b3)
{
    __shared__ float sW2[HN * HN];
    __shared__ float sW1a[HN], sW1b[HN], sb1[HN], sb2[HN], sW3[HN];
    __shared__ float sh1[PPB][H1S];

    const int tid = threadIdx.x;

    // load W2 (16 KB) vectorized
    {
        const float4* W24 = (const float4*)W2;
        float4* sW24 = (float4*)sW2;
#pragma unroll
        for (int t = tid; t < HN * HN / 4; t += 128) sW24[t] = W24[t];
    }
    if (tid < HN) {
        sW1a[tid] = W1[tid];        // W1[0][k]
        sW1b[tid] = W1[HN + tid];   // W1[1][k]
        sb1[tid]  = b1[tid];
        sb2[tid]  = b2[tid];
        sW3[tid]  = W3[tid];
    }
    __syncthreads();

    const int p = tid >> 4;          // point slot 0..7
    const int q = tid & 15;          // column quarter 0..15
    const int k = blockIdx.x * PPB + p;
    const int kc = min(k, TAB_ENTRIES);

    const float d2   = __int_as_float(TAB_BASE + (kc << TAB_SHIFT));
    const float dist = sqrtf(d2);
    const float invc = 1.0f / (d2 * dist);

    // phase 1: h1 for this point's a-range [q*4, q*4+4)
    {
        const int a0 = q * 4;
        float4 h;
        h.x = fmaxf(fmaf(dist, sW1a[a0 + 0], fmaf(invc, sW1b[a0 + 0], sb1[a0 + 0])), 0.0f);
        h.y = fmaxf(fmaf(dist, sW1a[a0 + 1], fmaf(invc, sW1b[a0 + 1], sb1[a0 + 1])), 0.0f);
        h.z = fmaxf(fmaf(dist, sW1a[a0 + 2], fmaf(invc, sW1b[a0 + 2], sb1[a0 + 2])), 0.0f);
        h.w = fmaxf(fmaf(dist, sW1a[a0 + 3], fmaf(invc, sW1b[a0 + 3], sb1[a0 + 3])), 0.0f);
        *(float4*)&sh1[p][a0] = h;
    }
    __syncthreads();

    // phase 2: GEMV slice, columns [c0, c0+4)
    const int c0 = q * 4;
    float ax = 0.f, ay = 0.f, az = 0.f, aw = 0.f;
#pragma unroll 8
    for (int a = 0; a < HN; a++) {
        float h = sh1[p][a];
        float4 w = *(const float4*)&sW2[a * HN + c0];
        ax = fmaf(h, w.x, ax);
        ay = fmaf(h, w.y, ay);
        az = fmaf(h, w.z, az);
        aw = fmaf(h, w.w, aw);
    }

    // phase 3: bias + relu + W3 dot, reduce over 16 lanes
    float m = fmaxf(ax + sb2[c0 + 0], 0.0f) * sW3[c0 + 0]
            + fmaxf(ay + sb2[c0 + 1], 0.0f) * sW3[c0 + 1]
            + fmaxf(az + sb2[c0 + 2], 0.0f) * sW3[c0 + 2]
            + fmaxf(aw + sb2[c0 + 3], 0.0f) * sW3[c0 + 3];
    m += __shfl_xor_sync(0xffffffffu, m, 1);
    m += __shfl_xor_sync(0xffffffffu, m, 2);
    m += __shfl_xor_sync(0xffffffffu, m, 4);
    m += __shfl_xor_sync(0xffffffffu, m, 8);

    if (q == 0 && k <= TAB_ENTRIES)
        g_vals[k] = m + __ldg(b3);
}

// ---------------------------------------------------------------------------
// Kernel 2 (fused): zero the output AND pack (intercept, slope) per interval.
// ---------------------------------------------------------------------------
__global__ __launch_bounds__(256)
void pack_zero_kernel(float* __restrict__ out, int out_n)
{
    int k = blockIdx.x * blockDim.x + threadIdx.x;
    if (k < out_n) out[k] = 0.0f;
    if (k < TAB_ENTRIES) {
        float x0 = __int_as_float(TAB_BASE + (k << TAB_SHIFT));
        float x1 = __int_as_float(TAB_BASE + ((k + 1) << TAB_SHIFT));
        float v0 = g_vals[k];
        float v1 = g_vals[k + 1];
        float s  = (v1 - v0) / (x1 - x0);
        g_tab[k] = make_float2(fmaf(-x0, s, v0), s);   // m(d2) = c0 + d2*s
    }
}

// ---------------------------------------------------------------------------
// Kernel 3: tiled all-pairs force accumulation.
//   acc_i = sum_j m(d2_ij) * (pos_j - pos_i)     (j==i term is exactly 0)
// ---------------------------------------------------------------------------
#define IT 128
#define JC 64

__global__ __launch_bounds__(IT)
void forces_kernel(const float* __restrict__ pos, float* __restrict__ out, int N)
{
    const int b  = blockIdx.z;
    const int i  = blockIdx.y * IT + threadIdx.x;
    const int j0 = blockIdx.x * JC;
    const float* p = pos + (size_t)b * N * 3;

    __shared__ float4 sj[JC];
    if (threadIdx.x < JC) {
        int j = j0 + threadIdx.x;
        sj[threadIdx.x] = make_float4(p[j * 3 + 0], p[j * 3 + 1], p[j * 3 + 2], 0.0f);
    }
    __syncthreads();

    const float xi = p[i * 3 + 0];
    const float yi = p[i * 3 + 1];
    const float zi = p[i * 3 + 2];

    float ax = 0.0f, ay = 0.0f, az = 0.0f;
    const float2* __restrict__ tab = g_tab;

#pragma unroll 16
    for (int t = 0; t < JC; t++) {
        float4 pj = sj[t];
        float dx = pj.x - xi;
        float dy = pj.y - yi;
        float dz = pj.z - zi;
        float d2 = fmaf(dx, dx, fmaf(dy, dy, fmaf(dz, dz, EPS2f)));

        // d2 >= EPS^2 > table base, so only the upper clamp is needed
        int bits = min(__float_as_int(d2), (int)TAB_TOP - 1);
        float2 ts = tab[(unsigned)(bits - (int)TAB_BASE) >> TAB_SHIFT];
        float m = fmaf(d2, ts.y, ts.x);

        ax = fmaf(m, dx, ax);
        ay = fmaf(m, dy, ay);
        az = fmaf(m, dz, az);
    }

    float* o = out + ((size_t)b * N + i) * 3;
    atomicAdd(o + 0, ax);
    atomicAdd(o + 1, ay);
    atomicAdd(o + 2, az);
}

// ---------------------------------------------------------------------------
// Launch
// ---------------------------------------------------------------------------
extern "C" void kernel_launch(void* const* d_in, const int* in_sizes, int n_in,
                              void* d_out, int out_size)
{
    const float* pos = (const float*)d_in[0];
    const float* W1  = (const float*)d_in[1];
    const float* b1  = (const float*)d_in[2];
    const float* W2  = (const float*)d_in[3];
    const float* b2  = (const float*)d_in[4];
    const float* W3  = (const float*)d_in[5];
    const float* b3  = (const float*)d_in[6];
    float* out = (float*)d_out;

    const int N = 2048;
    const int B = in_sizes[0] / (N * 3);   // = 2

    // 1) build m(d2) table: 8 points per 128-thread block
    {
        int blocks = (TAB_ENTRIES + 1 + PPB - 1) / PPB;
        build_table_kernel<<<blocks, 128>>>(W1, b1, W2, b2, W3, b3);
    }
    // 2) fused: zero output + pack (intercept, slope)
    {
        int threads = 256;
        int n = out_size > TAB_ENTRIES ? out_size : TAB_ENTRIES;
        pack_zero_kernel<<<(n + threads - 1) / threads, threads>>>(out, out_size);
    }
    // 3) main all-pairs accumulation
    {
        dim3 grid(N / JC, N / IT, B);
        forces_kernel<<<grid, IT>>>(pos, out, N);
    }
}

// round 8
// speedup vs baseline: 2.5527x; 1.0122x over previous
#include <cuda_runtime.h>
#include <cuda_bf16.h>
#include <math.h>

// Problem constants (B=2, N=2048, H=64, EPS=0.01)
#define HN 64
#define EPS2f 0.0001f

// Table over d2 in [~9.92e-5, 4096], indexed by float bit pattern.
// BASE aligned to 1<<SHIFT; 2^(23-SHIFT)=128 samples per binade.
#define TAB_SHIFT 16
#define TAB_BASE  0x38D00000        // 9.918e-5f  (< 1e-4 = EPS^2, so no lower clamp needed)
#define TAB_TOP   0x45800000        // 4096.0f
#define TAB_ENTRIES ((TAB_TOP - TAB_BASE) >> TAB_SHIFT)   // 3248

__device__ float  g_vals[TAB_ENTRIES + 1];
__device__ float2 g_tab[TAB_ENTRIES];   // (intercept c0 = v0 - x0*s, slope s)

// ---------------------------------------------------------------------------
// Kernel 1: evaluate MLP m(d2) at every grid point — cooperative version.
// 128 threads handle 8 points. Thread (p = tid>>4, q = tid&15):
//   phase 1: computes h1[p][q*4 .. q*4+4) into smem (padded stride 68)
//   phase 2: float4 GEMV slice over columns [q*4, q*4+4)
//   phase 3: relu + W3 dot, 16-lane shfl reduce, lane q==0 writes.
// ---------------------------------------------------------------------------
#define PPB 8
#define H1S 68   // padded h1 row stride (68*4B = 272B: 16B-aligned, bank-shifted)

__global__ __launch_bounds__(128)
void build_table_kernel(const float* __restrict__ W1, const float* __restrict__ b1,
                        const float* __restrict__ W2, const float* __restrict__ b2,
                        const float* __restrict__ W3, const float* __restrict__ b3)
{
    __shared__ float sW2[HN * HN];
    __shared__ float sW1a[HN], sW1b[HN], sb1[HN], sb2[HN], sW3[HN];
    __shared__ float sh1[PPB][H1S];

    const int tid = threadIdx.x;

    // load W2 (16 KB) vectorized
    {
        const float4* W24 = (const float4*)W2;
        float4* sW24 = (float4*)sW2;
#pragma unroll
        for (int t = tid; t < HN * HN / 4; t += 128) sW24[t] = W24[t];
    }
    if (tid < HN) {
        sW1a[tid] = W1[tid];        // W1[0][k]
        sW1b[tid] = W1[HN + tid];   // W1[1][k]
        sb1[tid]  = b1[tid];
        sb2[tid]  = b2[tid];
        sW3[tid]  = W3[tid];
    }
    __syncthreads();

    const int p = tid >> 4;          // point slot 0..7
    const int q = tid & 15;          // column quarter 0..15
    const int k = blockIdx.x * PPB + p;
    const int kc = min(k, TAB_ENTRIES);

    const float d2   = __int_as_float(TAB_BASE + (kc << TAB_SHIFT));
    const float dist = sqrtf(d2);
    const float invc = 1.0f / (d2 * dist);

    // phase 1: h1 for this point's a-range [q*4, q*4+4)
    {
        const int a0 = q * 4;
        float4 h;
        h.x = fmaxf(fmaf(dist, sW1a[a0 + 0], fmaf(invc, sW1b[a0 + 0], sb1[a0 + 0])), 0.0f);
        h.y = fmaxf(fmaf(dist, sW1a[a0 + 1], fmaf(invc, sW1b[a0 + 1], sb1[a0 + 1])), 0.0f);
        h.z = fmaxf(fmaf(dist, sW1a[a0 + 2], fmaf(invc, sW1b[a0 + 2], sb1[a0 + 2])), 0.0f);
        h.w = fmaxf(fmaf(dist, sW1a[a0 + 3], fmaf(invc, sW1b[a0 + 3], sb1[a0 + 3])), 0.0f);
        *(float4*)&sh1[p][a0] = h;
    }
    __syncthreads();

    // phase 2: GEMV slice, columns [c0, c0+4)
    const int c0 = q * 4;
    float ax = 0.f, ay = 0.f, az = 0.f, aw = 0.f;
#pragma unroll 8
    for (int a = 0; a < HN; a++) {
        float h = sh1[p][a];
        float4 w = *(const float4*)&sW2[a * HN + c0];
        ax = fmaf(h, w.x, ax);
        ay = fmaf(h, w.y, ay);
        az = fmaf(h, w.z, az);
        aw = fmaf(h, w.w, aw);
    }

    // phase 3: bias + relu + W3 dot, reduce over 16 lanes
    float m = fmaxf(ax + sb2[c0 + 0], 0.0f) * sW3[c0 + 0]
            + fmaxf(ay + sb2[c0 + 1], 0.0f) * sW3[c0 + 1]
            + fmaxf(az + sb2[c0 + 2], 0.0f) * sW3[c0 + 2]
            + fmaxf(aw + sb2[c0 + 3], 0.0f) * sW3[c0 + 3];
    m += __shfl_xor_sync(0xffffffffu, m, 1);
    m += __shfl_xor_sync(0xffffffffu, m, 2);
    m += __shfl_xor_sync(0xffffffffu, m, 4);
    m += __shfl_xor_sync(0xffffffffu, m, 8);

    if (q == 0 && k <= TAB_ENTRIES)
        g_vals[k] = m + __ldg(b3);
}

// ---------------------------------------------------------------------------
// Kernel 2 (fused): zero the output AND pack (intercept, slope) per interval.
// ---------------------------------------------------------------------------
__global__ __launch_bounds__(256)
void pack_zero_kernel(float* __restrict__ out, int out_n)
{
    int k = blockIdx.x * blockDim.x + threadIdx.x;
    if (k < out_n) out[k] = 0.0f;
    if (k < TAB_ENTRIES) {
        float x0 = __int_as_float(TAB_BASE + (k << TAB_SHIFT));
        float x1 = __int_as_float(TAB_BASE + ((k + 1) << TAB_SHIFT));
        float v0 = g_vals[k];
        float v1 = g_vals[k + 1];
        float s  = (v1 - v0) / (x1 - x0);
        g_tab[k] = make_float2(fmaf(-x0, s, v0), s);   // m(d2) = c0 + d2*s
    }
}

// ---------------------------------------------------------------------------
// Kernel 3: tiled all-pairs force accumulation.
//   acc_i = sum_j m(d2_ij) * (pos_j - pos_i)     (j==i term is exactly 0)
// ---------------------------------------------------------------------------
#define IT 128
#define JC 64

__global__ __launch_bounds__(IT)
void forces_kernel(const float* __restrict__ pos, float* __restrict__ out, int N)
{
    const int b  = blockIdx.z;
    const int i  = blockIdx.y * IT + threadIdx.x;
    const int j0 = blockIdx.x * JC;
    const float* p = pos + (size_t)b * N * 3;

    __shared__ float4 sj[JC];
    if (threadIdx.x < JC) {
        int j = j0 + threadIdx.x;
        sj[threadIdx.x] = make_float4(p[j * 3 + 0], p[j * 3 + 1], p[j * 3 + 2], 0.0f);
    }
    __syncthreads();

    const float xi = p[i * 3 + 0];
    const float yi = p[i * 3 + 1];
    const float zi = p[i * 3 + 2];

    float ax = 0.0f, ay = 0.0f, az = 0.0f;
    const float2* __restrict__ tab = g_tab;

#pragma unroll 16
    for (int t = 0; t < JC; t++) {
        float4 pj = sj[t];
        float dx = pj.x - xi;
        float dy = pj.y - yi;
        float dz = pj.z - zi;
        float d2 = fmaf(dx, dx, fmaf(dy, dy, fmaf(dz, dz, EPS2f)));

        // d2 >= EPS^2 > table base, so only the upper clamp is needed
        int bits = min(__float_as_int(d2), (int)TAB_TOP - 1);
        float2 ts = tab[(unsigned)(bits - (int)TAB_BASE) >> TAB_SHIFT];
        float m = fmaf(d2, ts.y, ts.x);

        ax = fmaf(m, dx, ax);
        ay = fmaf(m, dy, ay);
        az = fmaf(m, dz, az);
    }

    float* o = out + ((size_t)b * N + i) * 3;
    atomicAdd(o + 0, ax);
    atomicAdd(o + 1, ay);
    atomicAdd(o + 2, az);
}

// ---------------------------------------------------------------------------
// Launch
// ---------------------------------------------------------------------------
extern "C" void kernel_launch(void* const* d_in, const int* in_sizes, int n_in,
                              void* d_out, int out_size)
{
    const float* pos = (const float*)d_in[0];
    const float* W1  = (const float*)d_in[1];
    const float* b1  = (const float*)d_in[2];
    const float* W2  = (const float*)d_in[3];
    const float* b2  = (const float*)d_in[4];
    const float* W3  = (const float*)d_in[5];
    const float* b3  = (const float*)d_in[6];
    float* out = (float*)d_out;

    const int N = 2048;
    const int B = in_sizes[0] / (N * 3);   // = 2

    // 1) build m(d2) table: 8 points per 128-thread block
    {
        int blocks = (TAB_ENTRIES + 1 + PPB - 1) / PPB;
        build_table_kernel<<<blocks, 128>>>(W1, b1, W2, b2, W3, b3);
    }
    // 2) fused: zero output + pack (intercept, slope)
    {
        int threads = 256;
        int n = out_size > TAB_ENTRIES ? out_size : TAB_ENTRIES;
        pack_zero_kernel<<<(n + threads - 1) / threads, threads>>>(out, out_size);
    }
    // 3) main all-pairs accumulation
    {
        dim3 grid(N / JC, N / IT, B);
        forces_kernel<<<grid, IT>>>(pos, out, N);
    }
}

// round 9
// speedup vs baseline: 2.8339x; 1.1102x over previous
#include <cuda_runtime.h>
#include <cuda_bf16.h>
#include <math.h>

// Problem constants (B=2, N=2048, H=64, EPS=0.01)
#define HN 64
#define EPS2f 0.0001f

// Table over d2 in [~9.92e-5, 4096], indexed by float bit pattern.
// BASE aligned to 1<<SHIFT; 2^(23-SHIFT)=128 samples per binade.
#define TAB_SHIFT 16
#define TAB_BASE  0x38D00000        // 9.918e-5f  (< 1e-4 = EPS^2, so no lower clamp needed)
#define TAB_TOP   0x45800000        // 4096.0f
#define TAB_ENTRIES ((TAB_TOP - TAB_BASE) >> TAB_SHIFT)   // 3248

__device__ float  g_vals[TAB_ENTRIES + 1];
__device__ float2 g_tab[TAB_ENTRIES];   // (intercept c0 = v0 - x0*s, slope s)

// ---------------------------------------------------------------------------
// Kernel 1: evaluate MLP m(d2) at every grid point — cooperative version.
// 128 threads handle 8 points. Thread (p = tid>>4, q = tid&15):
//   phase 1: computes h1[p][q*4 .. q*4+4) into smem (padded stride 68)
//   phase 2: float4 GEMV slice over columns [q*4, q*4+4)
//   phase 3: relu + W3 dot, 16-lane shfl reduce, lane q==0 writes.
// ---------------------------------------------------------------------------
#define PPB 8
#define H1S 68   // padded h1 row stride (68*4B = 272B: 16B-aligned, bank-shifted)

__global__ __launch_bounds__(128)
void build_table_kernel(const float* __restrict__ W1, const float* __restrict__ b1,
                        const float* __restrict__ W2, const float* __restrict__ b2,
                        const float* __restrict__ W3, const float* __restrict__ b3)
{
    __shared__ float sW2[HN * HN];
    __shared__ float sW1a[HN], sW1b[HN], sb1[HN], sb2[HN], sW3[HN];
    __shared__ float sh1[PPB][H1S];

    const int tid = threadIdx.x;

    // load W2 (16 KB) vectorized
    {
        const float4* W24 = (const float4*)W2;
        float4* sW24 = (float4*)sW2;
#pragma unroll
        for (int t = tid; t < HN * HN / 4; t += 128) sW24[t] = W24[t];
    }
    if (tid < HN) {
        sW1a[tid] = W1[tid];        // W1[0][k]
        sW1b[tid] = W1[HN + tid];   // W1[1][k]
        sb1[tid]  = b1[tid];
        sb2[tid]  = b2[tid];
        sW3[tid]  = W3[tid];
    }
    __syncthreads();

    const int p = tid >> 4;          // point slot 0..7
    const int q = tid & 15;          // column quarter 0..15
    const int k = blockIdx.x * PPB + p;
    const int kc = min(k, TAB_ENTRIES);

    const float d2   = __int_as_float(TAB_BASE + (kc << TAB_SHIFT));
    const float dist = sqrtf(d2);
    const float invc = 1.0f / (d2 * dist);

    // phase 1: h1 for this point's a-range [q*4, q*4+4)
    {
        const int a0 = q * 4;
        float4 h;
        h.x = fmaxf(fmaf(dist, sW1a[a0 + 0], fmaf(invc, sW1b[a0 + 0], sb1[a0 + 0])), 0.0f);
        h.y = fmaxf(fmaf(dist, sW1a[a0 + 1], fmaf(invc, sW1b[a0 + 1], sb1[a0 + 1])), 0.0f);
        h.z = fmaxf(fmaf(dist, sW1a[a0 + 2], fmaf(invc, sW1b[a0 + 2], sb1[a0 + 2])), 0.0f);
        h.w = fmaxf(fmaf(dist, sW1a[a0 + 3], fmaf(invc, sW1b[a0 + 3], sb1[a0 + 3])), 0.0f);
        *(float4*)&sh1[p][a0] = h;
    }
    __syncthreads();

    // phase 2: GEMV slice, columns [c0, c0+4)
    const int c0 = q * 4;
    float ax = 0.f, ay = 0.f, az = 0.f, aw = 0.f;
#pragma unroll 8
    for (int a = 0; a < HN; a++) {
        float h = sh1[p][a];
        float4 w = *(const float4*)&sW2[a * HN + c0];
        ax = fmaf(h, w.x, ax);
        ay = fmaf(h, w.y, ay);
        az = fmaf(h, w.z, az);
        aw = fmaf(h, w.w, aw);
    }

    // phase 3: bias + relu + W3 dot, reduce over 16 lanes
    float m = fmaxf(ax + sb2[c0 + 0], 0.0f) * sW3[c0 + 0]
            + fmaxf(ay + sb2[c0 + 1], 0.0f) * sW3[c0 + 1]
            + fmaxf(az + sb2[c0 + 2], 0.0f) * sW3[c0 + 2]
            + fmaxf(aw + sb2[c0 + 3], 0.0f) * sW3[c0 + 3];
    m += __shfl_xor_sync(0xffffffffu, m, 1);
    m += __shfl_xor_sync(0xffffffffu, m, 2);
    m += __shfl_xor_sync(0xffffffffu, m, 4);
    m += __shfl_xor_sync(0xffffffffu, m, 8);

    if (q == 0 && k <= TAB_ENTRIES)
        g_vals[k] = m + __ldg(b3);
}

// ---------------------------------------------------------------------------
// Kernel 2 (fused): zero the output AND pack (intercept, slope) per interval.
// ---------------------------------------------------------------------------
__global__ __launch_bounds__(256)
void pack_zero_kernel(float* __restrict__ out, int out_n)
{
    int k = blockIdx.x * blockDim.x + threadIdx.x;
    if (k < out_n) out[k] = 0.0f;
    if (k < TAB_ENTRIES) {
        float x0 = __int_as_float(TAB_BASE + (k << TAB_SHIFT));
        float x1 = __int_as_float(TAB_BASE + ((k + 1) << TAB_SHIFT));
        float v0 = g_vals[k];
        float v1 = g_vals[k + 1];
        float s  = (v1 - v0) / (x1 - x0);
        g_tab[k] = make_float2(fmaf(-x0, s, v0), s);   // m(d2) = c0 + d2*s
    }
}

// ---------------------------------------------------------------------------
// Kernel 3: tiled all-pairs force accumulation.
//   acc_i = sum_j m(d2_ij) * (pos_j - pos_i)     (j==i term is exactly 0)
// ---------------------------------------------------------------------------
#define IT 128
#define JC 64

__global__ __launch_bounds__(IT)
void forces_kernel(const float* __restrict__ pos, float* __restrict__ out, int N)
{
    const int b  = blockIdx.z;
    const int i  = blockIdx.y * IT + threadIdx.x;
    const int j0 = blockIdx.x * JC;
    const float* p = pos + (size_t)b * N * 3;

    __shared__ float4 sj[JC];
    if (threadIdx.x < JC) {
        int j = j0 + threadIdx.x;
        sj[threadIdx.x] = make_float4(p[j * 3 + 0], p[j * 3 + 1], p[j * 3 + 2], 0.0f);
    }
    __syncthreads();

    const float xi = p[i * 3 + 0];
    const float yi = p[i * 3 + 1];
    const float zi = p[i * 3 + 2];

    float ax = 0.0f, ay = 0.0f, az = 0.0f;
    const float2* __restrict__ tab = g_tab;

#pragma unroll 16
    for (int t = 0; t < JC; t++) {
        float4 pj = sj[t];
        float dx = pj.x - xi;
        float dy = pj.y - yi;
        float dz = pj.z - zi;
        float d2 = fmaf(dx, dx, fmaf(dy, dy, fmaf(dz, dz, EPS2f)));

        // d2 >= EPS^2 > table base, so only the upper clamp is needed
        int bits = min(__float_as_int(d2), (int)TAB_TOP - 1);
        float2 ts = tab[(unsigned)(bits - (int)TAB_BASE) >> TAB_SHIFT];
        float m = fmaf(d2, ts.y, ts.x);

        ax = fmaf(m, dx, ax);
        ay = fmaf(m, dy, ay);
        az = fmaf(m, dz, az);
    }

    float* o = out + ((size_t)b * N + i) * 3;
    atomicAdd(o + 0, ax);
    atomicAdd(o + 1, ay);
    atomicAdd(o + 2, az);
}

// ---------------------------------------------------------------------------
// Launch
// ---------------------------------------------------------------------------
extern "C" void kernel_launch(void* const* d_in, const int* in_sizes, int n_in,
                              void* d_out, int out_size)
{
    const float* pos = (const float*)d_in[0];
    const float* W1  = (const float*)d_in[1];
    const float* b1  = (const float*)d_in[2];
    const float* W2  = (const float*)d_in[3];
    const float* b2  = (const float*)d_in[4];
    const float* W3  = (const float*)d_in[5];
    const float* b3  = (const float*)d_in[6];
    float* out = (float*)d_out;

    const int N = 2048;
    const int B = in_sizes[0] / (N * 3);   // = 2

    // 1) build m(d2) table: 8 points per 128-thread block
    {
        int blocks = (TAB_ENTRIES + 1 + PPB - 1) / PPB;
        build_table_kernel<<<blocks, 128>>>(W1, b1, W2, b2, W3, b3);
    }
    // 2) fused: zero output + pack (intercept, slope)
    {
        int threads = 256;
        int n = out_size > TAB_ENTRIES ? out_size : TAB_ENTRIES;
        pack_zero_kernel<<<(n + threads - 1) / threads, threads>>>(out, out_size);
    }
    // 3) main all-pairs accumulation
    {
        dim3 grid(N / JC, N / IT, B);
        forces_kernel<<<grid, IT>>>(pos, out, N);
    }
}